// round 1
// baseline (speedup 1.0000x reference)
#include <cuda_runtime.h>
#include <math_constants.h>

// Problem constants (fixed by setup_inputs)
#define BS   32
#define C    128
#define GN   256
#define S    16
#define G    (BS * GN)      // 8192 groups
#define NG   2              // groups per block (consecutive gn -> memory adjacent)
#define NB   (G / NG)       // 4096 blocks
#define MAXN 9              // bg + up to 8 fg instances (labels in [-1,8))
#define INVT 5.0f           // 1 / T, T = 0.2
#define WLOSS 0.1f

__device__ float2 g_part[G];   // per-group (gl*gv, gv)

__global__ __launch_bounds__(256)
void group_kernel(const int*   __restrict__ lab_g,   // [bs, Gn, S]
                  const float* __restrict__ feat_g,  // [bs, C, Gn, S]
                  const int*   __restrict__ idx_g,   // [bs, Gn, S]
                  const float* __restrict__ ctx)     // [1, C]
{
    __shared__ __align__(16) float4 st4[C][8];          // staged tile, XOR-swizzled, 16KB
    __shared__ __align__(16) float  Mrow[NG][MAXN][C];  // instance means, 9KB
    __shared__ int    slotOf[NG][S];
    __shared__ float  scaleOf[NG][S];
    __shared__ int    instNum[NG];
    __shared__ int    hasBg[NG];
    __shared__ float  liPart[NG][4];
    __shared__ int    cntS[NG][MAXN];
    __shared__ int    fglS[NG][8];

    const int t   = threadIdx.x;
    const int g0  = blockIdx.x * NG;       // first group of this block
    const int b   = g0 / GN;
    const int gn0 = g0 % GN;               // NG=2 and GN even -> no b crossing

    // ---------------- Phase 0: coalesced gmem -> smem staging ----------------
    // Tile = 128 channels x 32 floats (2 groups x 16 s, contiguous in gmem).
    // Warp-linear float4 index -> 512B contiguous per LDG instruction.
    {
        const float4* src = (const float4*)(feat_g + ((size_t)b * C * GN + gn0) * S);
        #pragma unroll
        for (int it = 0; it < 4; ++it) {
            int f4 = t + it * 256;          // 0..1023
            int c  = f4 >> 3;               // channel row
            int k  = f4 & 7;                // float4 within the 32-float run
            st4[c][k ^ (c & 7)] = src[(size_t)c * (GN * S / 4) + k];
        }
    }

    // ---------------- Phase 1: per-group slot metadata (serial) ----------------
    if ((t & 127) == 0) {
        const int gl  = t >> 7;
        const int grp = g0 + gl;
        const int* idx = idx_g + (size_t)grp * S;
        const int* lb  = lab_g + (size_t)grp * S;
        int iv[S], lv[S];
        #pragma unroll
        for (int s = 0; s < S; ++s) { iv[s] = idx[s]; lv[s] = lb[s]; }
        // u = number of distinct seed indices (over all S, any order)
        int u = 0;
        for (int i = 0; i < S; ++i) {
            bool dup = false;
            for (int j = 0; j < i; ++j) dup |= (iv[j] == iv[i]);
            u += dup ? 0 : 1;
        }
        for (int k = 0; k < MAXN; ++k) cntS[gl][k] = 0;
        int nfg = 0; bool hb = false;
        for (int s = 0; s < S; ++s) {
            int slot = -1;
            if (s < u) {                    // truncate to first u samples
                int L = lv[s];
                if (L < 0) { slot = 0; hb = true; }
                else {
                    int k = -1;
                    for (int q = 0; q < nfg; ++q) if (fglS[gl][q] == L) k = q;
                    if (k < 0) { k = nfg; fglS[gl][nfg++] = L; }
                    slot = k + 1;
                }
                cntS[gl][slot]++;
            }
            slotOf[gl][s] = slot;
        }
        for (int s = 0; s < S; ++s) {
            int sl = slotOf[gl][s];
            scaleOf[gl][s] = (sl >= 0) ? 1.0f / (float)cntS[gl][sl] : 0.0f;
        }
        instNum[gl] = nfg + 1;
        hasBg[gl]   = hb ? 1 : 0;
    }
    __syncthreads();

    // ---------------- Phase 2: per-instance means (thread = one channel col) ----------------
    {
        const int gl = t >> 7;
        const int c  = t & 127;
        #pragma unroll
        for (int k = 0; k < MAXN; ++k) Mrow[gl][k][c] = 0.0f;
        float f[S];
        #pragma unroll
        for (int q = 0; q < 4; ++q) {
            float4 v = st4[c][(gl * 4 + q) ^ (c & 7)];
            f[q*4+0] = v.x; f[q*4+1] = v.y; f[q*4+2] = v.z; f[q*4+3] = v.w;
        }
        #pragma unroll
        for (int s = 0; s < S; ++s) {
            int sl = slotOf[gl][s];
            if (sl >= 0) Mrow[gl][sl][c] += f[s] * scaleOf[gl][s];   // owns column c: race-free
        }
        if (!hasBg[gl]) Mrow[gl][0][c] = __ldg(ctx + c);             // ctx replaces missing bg
    }
    __syncthreads();

    // ---------------- Phase 3: sim rows + logsumexp (warp = 2 fg rows) ----------------
    {
        const int w    = t >> 5;       // 0..7
        const int gl   = w >> 2;
        const int r    = w & 3;
        const int lane = t & 31;
        const int n    = instNum[gl];
        const int i1   = 1 + r;
        const int i2   = 5 + r;
        float li = 0.0f;
        if (i1 < n) {
            const float4* Mv = (const float4*)&Mrow[gl][0][0];       // rows of 32 float4
            float4 a1 = Mv[i1 * 32 + lane];
            const bool v2 = (i2 < n);
            float4 a2 = v2 ? Mv[i2 * 32 + lane] : make_float4(0.f,0.f,0.f,0.f);
            float d1 = -CUDART_INF_F, d2 = -CUDART_INF_F;
            for (int j = 0; j < n; ++j) {
                float4 bb = Mv[j * 32 + lane];
                float p1 = a1.x*bb.x + a1.y*bb.y + a1.z*bb.z + a1.w*bb.w;
                float p2 = a2.x*bb.x + a2.y*bb.y + a2.z*bb.z + a2.w*bb.w;
                #pragma unroll
                for (int o = 16; o > 0; o >>= 1) {
                    p1 += __shfl_xor_sync(0xffffffffu, p1, o);
                    p2 += __shfl_xor_sync(0xffffffffu, p2, o);
                }
                if (lane == j) { d1 = p1 * INVT; d2 = p2 * INVT; }
            }
            // row i1
            {
                float m = d1;
                #pragma unroll
                for (int o = 16; o > 0; o >>= 1) m = fmaxf(m, __shfl_xor_sync(0xffffffffu, m, o));
                float e = __expf(d1 - m);        // lanes >= n: d1 = -inf -> e = 0
                float ss = e;
                #pragma unroll
                for (int o = 16; o > 0; o >>= 1) ss += __shfl_xor_sync(0xffffffffu, ss, o);
                float lse = m + __logf(ss);
                float di  = __shfl_sync(0xffffffffu, d1, i1);
                li += lse - di;
            }
            if (v2) {
                float m = d2;
                #pragma unroll
                for (int o = 16; o > 0; o >>= 1) m = fmaxf(m, __shfl_xor_sync(0xffffffffu, m, o));
                float e = __expf(d2 - m);
                float ss = e;
                #pragma unroll
                for (int o = 16; o > 0; o >>= 1) ss += __shfl_xor_sync(0xffffffffu, ss, o);
                float lse = m + __logf(ss);
                float di  = __shfl_sync(0xffffffffu, d2, i2);
                li += lse - di;
            }
        }
        if (lane == 0) liPart[gl][r] = li;
    }
    __syncthreads();

    // ---------------- Phase 4: per-group loss ----------------
    if ((t & 127) == 0) {
        const int gl = t >> 7;
        float lsum = liPart[gl][0] + liPart[gl][1] + liPart[gl][2] + liPart[gl][3];
        int fg = instNum[gl] - 1;
        float valid = (fg >= 1) ? 1.0f : 0.0f;
        float glv = lsum / (float)((fg >= 1) ? fg : 1);
        g_part[g0 + gl] = make_float2(glv * valid, valid);
    }
}

__global__ void reduce_kernel(float* __restrict__ out)
{
    __shared__ float sx[256], sy[256];
    const int t = threadIdx.x;
    float ax = 0.0f, ay = 0.0f;
    for (int i = t; i < G; i += 256) {
        float2 p = g_part[i];
        ax += p.x; ay += p.y;
    }
    sx[t] = ax; sy[t] = ay;
    __syncthreads();
    for (int o = 128; o > 0; o >>= 1) {
        if (t < o) { sx[t] += sx[t + o]; sy[t] += sy[t + o]; }
        __syncthreads();
    }
    if (t == 0) out[0] = sx[0] / sy[0] * WLOSS;
}

extern "C" void kernel_launch(void* const* d_in, const int* in_sizes, int n_in,
                              void* d_out, int out_size)
{
    const int*   lab  = (const int*)  d_in[0];   // proposal_instance_mask
    const float* feat = (const float*)d_in[1];   // grouped_features
    const int*   idx  = (const int*)  d_in[2];   // grouped_indices
    const float* ctx  = (const float*)d_in[3];   // context_compen
    (void)in_sizes; (void)n_in; (void)out_size;

    group_kernel<<<NB, 256>>>(lab, feat, idx, ctx);
    reduce_kernel<<<1, 256>>>((float*)d_out);
}

// round 3
// speedup vs baseline: 1.3308x; 1.3308x over previous
#include <cuda_runtime.h>
#include <math_constants.h>

// Problem constants (fixed by setup_inputs)
#define BS   32
#define C    128
#define GN   256
#define S    16
#define G    (BS * GN)      // 8192 groups
#define NG   2              // groups per block (consecutive gn -> memory adjacent)
#define NB   (G / NG)       // 4096 blocks
#define MAXN 9              // bg + up to 8 fg instances (labels in [-1,8))
#define INVT 5.0f           // 1 / T, T = 0.2
#define WLOSS 0.1f

__device__ float2   g_part[G];   // per-group (gl*gv, gv)
__device__ unsigned g_ctr = 0;   // completed-block counter (self-resetting)

__global__ __launch_bounds__(256, 4)
void fused_kernel(const int*   __restrict__ lab_g,   // [bs, Gn, S]
                  const float* __restrict__ feat_g,  // [bs, C, Gn, S]
                  const int*   __restrict__ idx_g,   // [bs, Gn, S]
                  const float* __restrict__ ctx,     // [1, C]
                  float*       __restrict__ out)
{
    __shared__ __align__(16) float4 st4[C][8];          // staged tile, XOR-swizzled, 16KB
    __shared__ __align__(16) float  Mrow[NG][MAXN][C];  // instance means, 9KB
    __shared__ float2 ss2[NG][S];                       // (scale, slot-as-float)
    __shared__ int    instNum[NG];
    __shared__ int    hasBg[NG];
    __shared__ float  liPart[NG][4];
    __shared__ int    sIsLast;
    __shared__ float  red[16];

    const int t   = threadIdx.x;
    const int g0  = blockIdx.x * NG;
    const int b   = g0 / GN;
    const int gn0 = g0 % GN;

    // ---------------- Phase 0: coalesced gmem -> smem staging ----------------
    {
        const float4* src = (const float4*)(feat_g + ((size_t)b * C * GN + gn0) * S);
        #pragma unroll
        for (int it = 0; it < 4; ++it) {
            int f4 = t + it * 256;          // 0..1023
            int c  = f4 >> 3;
            int k  = f4 & 7;
            st4[c][k ^ (c & 7)] = src[(size_t)c * (GN * S / 4) + k];
        }
    }

    // ---------------- Phase 1: warp-parallel slot metadata (warps 0,1) ----------------
    if (t < 64) {
        const int  w    = t >> 5;           // local group
        const int  lane = t & 31;
        const int  grp  = g0 + w;
        const bool sm   = lane < S;
        // lanes >= S carry unique sentinels so they never match real values
        int myIdx = sm ? idx_g[(size_t)grp * S + lane] : (0x40000000 | lane);
        int myLab = sm ? lab_g[(size_t)grp * S + lane] : 0;
        unsigned mi    = __match_any_sync(0xffffffffu, myIdx);
        bool     leadI = sm && (lane == (__ffs(mi) - 1));
        int      u     = __popc(__ballot_sync(0xffffffffu, leadI));   // distinct seed idx count
        bool     valid = sm && (lane < u);
        int      labm  = valid ? myLab : (0x41000000 | lane);
        unsigned ml    = __match_any_sync(0xffffffffu, labm);
        bool     isBg  = valid && (myLab < 0);
        bool     isFg  = valid && (myLab >= 0);
        int      leadLane = __ffs(ml) - 1;
        unsigned fgLead   = __ballot_sync(0xffffffffu, isFg && (lane == leadLane));
        unsigned bgB      = __ballot_sync(0xffffffffu, isBg);
        int      nfg      = __popc(fgLead);
        int   slot  = -1;
        float scale = 0.0f;
        if (valid) {
            scale = 1.0f / (float)__popc(ml);   // ml only holds matching (valid) lanes
            slot  = isBg ? 0 : (1 + __popc(fgLead & ((1u << leadLane) - 1u)));
        }
        if (sm) ss2[w][lane] = make_float2(scale, __int_as_float(slot));
        if (lane == 0) { instNum[w] = nfg + 1; hasBg[w] = (bgB != 0); }
    }
    __syncthreads();

    // ---------------- Phase 2: per-instance means (thread = one channel col) ----------------
    {
        const int gl = t >> 7;
        const int c  = t & 127;
        float f[S];
        #pragma unroll
        for (int q = 0; q < 4; ++q) {
            float4 v = st4[c][(gl * 4 + q) ^ (c & 7)];
            f[q*4+0] = v.x; f[q*4+1] = v.y; f[q*4+2] = v.z; f[q*4+3] = v.w;
        }
        #pragma unroll
        for (int k = 0; k < MAXN; ++k) Mrow[gl][k][c] = 0.0f;
        #pragma unroll
        for (int s = 0; s < S; ++s) {
            float2 v  = ss2[gl][s];
            int    sl = __float_as_int(v.y);
            if (sl >= 0) Mrow[gl][sl][c] += f[s] * v.x;   // owns column c: race-free
        }
        if (!hasBg[gl]) Mrow[gl][0][c] = __ldg(ctx + c);
    }
    __syncthreads();

    // ---------------- Phase 3: sim rows + logsumexp (warp = 2 fg rows) ----------------
    {
        const int w    = t >> 5;
        const int lane = t & 31;
        const int gl   = w >> 2;
        const int r    = w & 3;
        const int n    = instNum[gl];
        const int i1   = 1 + r;
        const int i2   = 5 + r;
        float li = 0.0f;
        if (i1 < n) {
            const float4* Mv = (const float4*)&Mrow[gl][0][0];   // 32 float4 per row
            float4 a1 = Mv[i1 * 32 + lane];
            const bool v2 = (i2 < n);
            float4 a2 = v2 ? Mv[i2 * 32 + lane] : make_float4(0.f,0.f,0.f,0.f);
            float p1[MAXN], p2[MAXN];
            #pragma unroll
            for (int j = 0; j < MAXN; ++j) {
                float4 bb = Mv[j * 32 + lane];   // rows >= n are zero-initialized: safe
                p1[j] = a1.x*bb.x + a1.y*bb.y + a1.z*bb.z + a1.w*bb.w;
                p2[j] = a2.x*bb.x + a2.y*bb.y + a2.z*bb.z + a2.w*bb.w;
            }
            // stage-parallel butterfly: 9 independent chains per row -> high ILP
            #pragma unroll
            for (int o = 16; o > 0; o >>= 1) {
                #pragma unroll
                for (int j = 0; j < MAXN; ++j) {
                    p1[j] += __shfl_xor_sync(0xffffffffu, p1[j], o);
                    p2[j] += __shfl_xor_sync(0xffffffffu, p2[j], o);
                }
            }
            // lse fully in registers (replicated across lanes, shfl-free)
            float m1 = -CUDART_INF_F, m2 = -CUDART_INF_F;
            #pragma unroll
            for (int j = 0; j < MAXN; ++j) {
                p1[j] = (j < n) ? p1[j] * INVT : -CUDART_INF_F;
                p2[j] = (j < n) ? p2[j] * INVT : -CUDART_INF_F;
                m1 = fmaxf(m1, p1[j]);
                m2 = fmaxf(m2, p2[j]);
            }
            float s1 = 0.f, s2 = 0.f, diag1 = 0.f, diag2 = 0.f;
            #pragma unroll
            for (int j = 0; j < MAXN; ++j) {
                s1 += __expf(p1[j] - m1);
                s2 += __expf(p2[j] - m2);
                if (j == i1) diag1 = p1[j];
                if (j == i2) diag2 = p2[j];
            }
            li = m1 + __logf(s1) - diag1;
            if (v2) li += m2 + __logf(s2) - diag2;
        }
        if (lane == 0) liPart[gl][r] = li;
    }
    __syncthreads();

    // ---------------- Phase 4: per-group loss + completion signal ----------------
    if (t == 0) {
        #pragma unroll
        for (int gl = 0; gl < NG; ++gl) {
            float ls = liPart[gl][0] + liPart[gl][1] + liPart[gl][2] + liPart[gl][3];
            int   fg = instNum[gl] - 1;
            float valid = (fg >= 1) ? 1.0f : 0.0f;
            float glv   = (fg >= 1) ? (ls / (float)fg) : 0.0f;
            g_part[g0 + gl] = make_float2(glv * valid, valid);
        }
        __threadfence();                       // publish g_part before signaling
        unsigned o = atomicAdd(&g_ctr, 1u);
        sIsLast = (o == (unsigned)(NB - 1));
    }
    __syncthreads();

    // ---------------- Phase 5: last block performs the (deterministic) final reduce ----------------
    if (sIsLast) {
        if (t == 0) __threadfence();           // acquire all g_part writes
        __syncthreads();
        const float4* gp = (const float4*)g_part;   // 2048 float4 = 4096 float2... (G/2 float4)
        float ax = 0.0f, ay = 0.0f;
        #pragma unroll 4
        for (int i = t; i < G / 2; i += 256) {
            float4 v = gp[i];
            ax += v.x + v.z;
            ay += v.y + v.w;
        }
        #pragma unroll
        for (int o = 16; o > 0; o >>= 1) {
            ax += __shfl_xor_sync(0xffffffffu, ax, o);
            ay += __shfl_xor_sync(0xffffffffu, ay, o);
        }
        if ((t & 31) == 0) { red[t >> 5] = ax; red[8 + (t >> 5)] = ay; }
        __syncthreads();
        if (t == 0) {
            float sx = 0.f, sy = 0.f;
            #pragma unroll
            for (int q = 0; q < 8; ++q) { sx += red[q]; sy += red[8 + q]; }
            out[0] = sx / sy * WLOSS;
            atomicExch(&g_ctr, 0u);            // visible reset for next graph replay
        }
    }
}

extern "C" void kernel_launch(void* const* d_in, const int* in_sizes, int n_in,
                              void* d_out, int out_size)
{
    const int*   lab  = (const int*)  d_in[0];   // proposal_instance_mask
    const float* feat = (const float*)d_in[1];   // grouped_features
    const int*   idx  = (const int*)  d_in[2];   // grouped_indices
    const float* ctx  = (const float*)d_in[3];   // context_compen
    (void)in_sizes; (void)n_in; (void)out_size;

    fused_kernel<<<NB, 256>>>(lab, feat, idx, ctx, (float*)d_out);
}